// round 15
// baseline (speedup 1.0000x reference)
#include <cuda_runtime.h>
#include <cuda_fp16.h>
#include <cstdint>

#define BATCH   8
#define SEQ     8192
#define BT      65536
#define DIM     512
#define HEADS   8
#define HD      64
#define KSLOTS  64
#define SCALE   0.125f
#define EPS_C   1e-20f
#define LN_EPS  1e-5f

#define NTOT    1024        // [logits(512) | V(512)]
#define MT      128
#define NT      128
#define KC      64          // k-chunk (halves)
#define NCHUNK  8           // 512/64

// ---------------- scratch ----------------
__device__ float d_S[KSLOTS * DIM];
__device__ float d_Weff[DIM * DIM];
__device__ float d_beff[DIM];
__device__ float d_bcat[NTOT];
__device__ __half d_Xh[(size_t)BT * DIM];
__device__ __half d_Wh[(size_t)NTOT * DIM];
__device__ __half d_LVh[(size_t)BT * NTOT];
__device__ float d_Num[BATCH * DIM * HD];
__device__ float d_C[BATCH * DIM];

// ---------------- helpers ----------------
__device__ __forceinline__ uint32_t s2u(const void* p) {
    uint32_t a;
    asm("{ .reg .u64 t; cvta.to.shared.u64 t, %1; cvt.u32.u64 %0, t; }" : "=r"(a) : "l"(p));
    return a;
}
// swizzled dword index within a [rows][32-dword] tile
#define SIDX(r, c) (((r) << 5) + ((c) ^ (((r) & 7) << 2)))

#define LDSM4(r0, r1, r2, r3, addr) \
    asm volatile("ldmatrix.sync.aligned.m8n8.x4.shared.b16 {%0,%1,%2,%3}, [%4];" \
        : "=r"(r0), "=r"(r1), "=r"(r2), "=r"(r3) : "r"(addr))

#define LDSM4T(r0, r1, r2, r3, addr) \
    asm volatile("ldmatrix.sync.aligned.m8n8.x4.trans.shared.b16 {%0,%1,%2,%3}, [%4];" \
        : "=r"(r0), "=r"(r1), "=r"(r2), "=r"(r3) : "r"(addr))

// NOTE: NOT volatile — pure register op with full constraints; lets ptxas
// interleave HMMA with the (volatile) LDSMs of the next k-step.
#define MMA16816(d, a, b0, b1) \
    asm( \
        "mma.sync.aligned.m16n8k16.row.col.f32.f16.f16.f32 " \
        "{%0,%1,%2,%3}, {%4,%5,%6,%7}, {%8,%9}, {%0,%1,%2,%3};" \
        : "+f"((d)[0]), "+f"((d)[1]), "+f"((d)[2]), "+f"((d)[3]) \
        : "r"((a)[0]), "r"((a)[1]), "r"((a)[2]), "r"((a)[3]), "r"(b0), "r"(b1))

__device__ __forceinline__ uint4 pack8(float4 a, float4 b) {
    __half2 p0 = __floats2half2_rn(a.x, a.y);
    __half2 p1 = __floats2half2_rn(a.z, a.w);
    __half2 p2 = __floats2half2_rn(b.x, b.y);
    __half2 p3 = __floats2half2_rn(b.z, b.w);
    uint4 o;
    o.x = *(uint32_t*)&p0; o.y = *(uint32_t*)&p1;
    o.z = *(uint32_t*)&p2; o.w = *(uint32_t*)&p3;
    return o;
}

__device__ __forceinline__ float blockReduceSum(float v, float* sbuf) {
    #pragma unroll
    for (int o = 16; o > 0; o >>= 1) v += __shfl_down_sync(0xffffffffu, v, o);
    int lane = threadIdx.x & 31, w = threadIdx.x >> 5;
    if (lane == 0) sbuf[w] = v;
    __syncthreads();
    int nw = blockDim.x >> 5;
    v = (threadIdx.x < nw) ? sbuf[threadIdx.x] : 0.f;
    if (w == 0) {
        #pragma unroll
        for (int o = 16; o > 0; o >>= 1) v += __shfl_down_sync(0xffffffffu, v, o);
    }
    if (threadIdx.x == 0) sbuf[0] = v;
    __syncthreads();
    v = sbuf[0];
    __syncthreads();
    return v;
}

// ---------------- 1. layernorm slots ----------------
__global__ void ln_slots_kernel(const float* __restrict__ slots,
                                const float* __restrict__ g,
                                const float* __restrict__ b) {
    __shared__ float sbuf[32];
    int k = blockIdx.x, tid = threadIdx.x;
    float x = slots[k * DIM + tid];
    float mu = blockReduceSum(x, sbuf) * (1.f / DIM);
    float dv = x - mu;
    float var = blockReduceSum(dv * dv, sbuf) * (1.f / DIM);
    d_S[k * DIM + tid] = dv * rsqrtf(var + LN_EPS) * g[tid] + b[tid];
}

// ---------------- 2. fold Q into Wk ----------------
__global__ void fold_kernel(const float* __restrict__ Wk,
                            const float* __restrict__ bk) {
    int rk = blockIdx.x;
    int h = rk >> 6, k = rk & 63;
    __shared__ float sq[HD];
    int tid = threadIdx.x;
    if (tid < HD) sq[tid] = d_S[k * DIM + h * HD + tid];
    __syncthreads();
    for (int j = tid; j < DIM; j += blockDim.x) {
        float acc = 0.f;
        #pragma unroll
        for (int d = 0; d < HD; d++)
            acc = fmaf(sq[d], Wk[(size_t)(h * HD + d) * DIM + j], acc);
        d_Weff[(size_t)rk * DIM + j] = acc * SCALE;
    }
    if (tid == 0) {
        float acc = 0.f;
        #pragma unroll
        for (int d = 0; d < HD; d++) acc += sq[d] * bk[h * HD + d];
        d_beff[rk] = acc * SCALE;
    }
}

// ---------------- 3. merged fp32 -> fp16 conversion + accumulator zeroing ----------------
#define CONVX_BLKS 16384
#define CONVW_BLKS 256
#define ZERO_BLKS  256
__global__ void conv_all(const float* __restrict__ X,
                         const float* __restrict__ Wv,
                         const float* __restrict__ bv) {
    if (blockIdx.x < CONVX_BLKS) {
        size_t idx = (size_t)blockIdx.x * 256 + threadIdx.x;
        size_t base = idx * 8;
        float4 a = *(const float4*)&X[base];
        float4 b = *(const float4*)&X[base + 4];
        *(uint4*)&d_Xh[base] = pack8(a, b);
    } else if (blockIdx.x < CONVX_BLKS + CONVW_BLKS) {
        size_t idx = (size_t)(blockIdx.x - CONVX_BLKS) * 256 + threadIdx.x;
        int row = (int)(idx >> 6);
        int c8 = ((int)idx & 63) << 3;
        const float* src = (row < 512) ? &d_Weff[(size_t)row * DIM + c8]
                                       : &Wv[(size_t)(row - 512) * DIM + c8];
        float4 a = *(const float4*)src;
        float4 b = *(const float4*)(src + 4);
        *(uint4*)&d_Wh[(size_t)row * DIM + c8] = pack8(a, b);
        if (c8 == 0) d_bcat[row] = (row < 512) ? d_beff[row] : bv[row - 512];
    } else {
        int z = blockIdx.x - CONVX_BLKS - CONVW_BLKS;
        float4 zero4 = {0.f, 0.f, 0.f, 0.f};
        *(float4*)&d_Num[((size_t)z * 256 + threadIdx.x) * 4] = zero4;
        if (z == 0) {
            #pragma unroll
            for (int i = 0; i < 16; i++) d_C[threadIdx.x + i * 256] = 0.f;
        }
    }
}

// ---------------- 4. fp16 mma GEMM (scheduler-free MMA) + fused softmax ----------------
// byte offsets: A stages s*16384 (3x16KB); B stages 49152 + s*16384; bias @98304
#define SMB_B0       49152
#define SMD_BIAS     24576            // dword index of bias (= byte 98304)
#define SMEM_BYTES   ((24576 + 128) * 4)

__device__ __forceinline__ void load_chunk(uint32_t adst, uint32_t bdst,
                                           const __half* __restrict__ a,
                                           const __half* __restrict__ b) {
    #pragma unroll
    for (int l = 0; l < 4; l++) {
        asm volatile("cp.async.cg.shared.global [%0], [%1], 16;"
                     :: "r"(adst + l * 4096), "l"(a + (size_t)l * 32 * DIM));
        asm volatile("cp.async.cg.shared.global [%0], [%1], 16;"
                     :: "r"(bdst + l * 4096), "l"(b + (size_t)l * 32 * DIM));
    }
    asm volatile("cp.async.commit_group;" ::: "memory");
}

__global__ void __launch_bounds__(256, 2) gemm_fp16(const __half* __restrict__ Xh,
                                                    const __half* __restrict__ Wh,
                                                    const float* __restrict__ bias,
                                                    __half* __restrict__ out) {
    extern __shared__ uint32_t sm32[];
    float* smf = (float*)sm32;
    uint32_t sb = s2u(sm32);
    const int tid = threadIdx.x;
    const int wid = tid >> 5, lane = tid & 31;
    const int g = lane >> 2, tg = lane & 3;
    const int q1 = (lane >> 3) & 1;     // +8-row select
    const int q2 = lane >> 4;           // k-chunk select
    const int wm = (wid & 3) * 32;      // 4 warp rows
    const int wn = (wid >> 2) * 64;     // 2 warp cols
    const int m0 = blockIdx.y * MT;
    const int n0 = blockIdx.x * NT;

    if (tid < NT) smf[SMD_BIAS + tid] = bias[n0 + tid];

    // ---- hoisted loader state (per-thread, chunk-invariant) ----
    const int lr = tid >> 3, lc = tid & 7;
    const __half* aptr = Xh + (size_t)(m0 + lr) * DIM + lc * 8;
    const __half* bptr = Wh + (size_t)(n0 + lr) * DIM + lc * 8;
    const uint32_t ldst = (uint32_t)SIDX(lr, lc * 4) * 4;

    // ---- fully precomputed fragment addresses ----
    const int fr = q1 * 8 + (lane & 7);
    uint32_t aadr[2][4], badr[4][4];
    #pragma unroll
    for (int mt = 0; mt < 2; mt++) {
        uint32_t off = (uint32_t)SIDX(wm + mt * 16 + fr, q2 * 4) * 4;
        #pragma unroll
        for (int ks = 0; ks < 4; ks++)
            aadr[mt][ks] = sb + (off ^ (uint32_t)(ks * 32));
    }
    #pragma unroll
    for (int p = 0; p < 4; p++) {
        uint32_t off = (uint32_t)SIDX(wn + p * 16 + fr, q2 * 4) * 4;
        #pragma unroll
        for (int ks = 0; ks < 4; ks++)
            badr[p][ks] = sb + SMB_B0 + (off ^ (uint32_t)(ks * 32));
    }

    float d[2][8][4];
    #pragma unroll
    for (int mt = 0; mt < 2; mt++)
        #pragma unroll
        for (int nt = 0; nt < 8; nt++)
            #pragma unroll
            for (int i = 0; i < 4; i++) d[mt][nt][i] = 0.f;

    load_chunk(sb + ldst,         sb + ldst + SMB_B0,         aptr,      bptr);
    load_chunk(sb + ldst + 16384, sb + ldst + SMB_B0 + 16384, aptr + KC, bptr + KC);

    // single barrier per chunk: wait -> sync -> issue next load -> compute
    #pragma unroll
    for (int c = 0; c < NCHUNK; c++) {
        const int s = c % 3;                       // compile-time after unroll
        if (c < NCHUNK - 1) asm volatile("cp.async.wait_group 1;" ::: "memory");
        else                asm volatile("cp.async.wait_group 0;" ::: "memory");
        __syncthreads();
        if (c + 2 < NCHUNK) {
            const int sp = (c + 2) % 3;            // == (c-1)%3: compute done pre-barrier
            load_chunk(sb + ldst + sp * 16384, sb + ldst + SMB_B0 + sp * 16384,
                       aptr + (c + 2) * KC, bptr + (c + 2) * KC);
        }

        const uint32_t simm = (uint32_t)(s * 16384);
        #pragma unroll
        for (int ks = 0; ks < 4; ks++) {
            uint32_t a[2][4], bfr[8][2];
            #pragma unroll
            for (int mt = 0; mt < 2; mt++)
                LDSM4(a[mt][0], a[mt][1], a[mt][2], a[mt][3], aadr[mt][ks] + simm);
            #pragma unroll
            for (int p = 0; p < 4; p++)
                LDSM4(bfr[2*p][0], bfr[2*p+1][0], bfr[2*p][1], bfr[2*p+1][1],
                      badr[p][ks] + simm);
            #pragma unroll
            for (int mt = 0; mt < 2; mt++)
                #pragma unroll
                for (int nt = 0; nt < 8; nt++)
                    MMA16816(d[mt][nt], a[mt], bfr[nt][0], bfr[nt][1]);
        }
    }
    __syncthreads();      // all compute done before epilogue overwrites stage smem

    // ---------------- epilogue: all 8 warps tile 128x128 disjointly ----------------
    #pragma unroll
    for (int mt = 0; mt < 2; mt++) {
        int r = wm + mt * 16 + g;
        #pragma unroll
        for (int nt = 0; nt < 8; nt++) {
            int cl = wn + nt * 8 + tg * 2;
            float b0 = smf[SMD_BIAS + cl];
            float b1 = smf[SMD_BIAS + cl + 1];
            float2 v0 = {d[mt][nt][0] + b0, d[mt][nt][1] + b1};
            float2 v1 = {d[mt][nt][2] + b0, d[mt][nt][3] + b1};
            *(float2*)&smf[r * 132 + cl]       = v0;
            *(float2*)&smf[(r + 8) * 132 + cl] = v1;
        }
    }
    __syncthreads();

    if (blockIdx.x < 4) {       // logits region: softmax per 64-col head group
        int r = tid >> 1, hg = tid & 1;
        const float* row = smf + r * 132 + hg * 64;
        float v[64];
        float m = row[0];
        #pragma unroll
        for (int i = 0; i < 64; i++) { v[i] = row[i]; m = fmaxf(m, v[i]); }
        float ssum = 0.f;
        #pragma unroll
        for (int i = 0; i < 64; i++) { v[i] = expf(v[i] - m); ssum += v[i]; }
        float inv = 1.f / ssum;
        __half* op = out + (size_t)(m0 + r) * NTOT + n0 + hg * 64;
        #pragma unroll
        for (int i = 0; i < 64; i += 8) {
            float4 a = {v[i] * inv, v[i+1] * inv, v[i+2] * inv, v[i+3] * inv};
            float4 b = {v[i+4] * inv, v[i+5] * inv, v[i+6] * inv, v[i+7] * inv};
            *(uint4*)(op + i) = pack8(a, b);
        }
    } else {                    // V region: plain fp16 store
        for (int i = tid; i < 128 * 16; i += 256) {
            int r = i >> 4, c8 = (i & 15) * 8;
            float4 a = *(const float4*)&smf[r * 132 + c8];
            float4 b = *(const float4*)&smf[r * 132 + c8 + 4];
            *(uint4*)&out[(size_t)(m0 + r) * NTOT + n0 + c8] = pack8(a, b);
        }
    }
}

// ---------------- 6. tensor-core accum: Num = W^T V, C = colsum(W) ----------------
__device__ __forceinline__ void acc_load(uint32_t wbase, uint32_t vbase,
                                         size_t grow0, int h, int ch, int buf, int tid) {
    #pragma unroll
    for (int l = 0; l < 4; l++) {
        int t = tid + l * 128;
        int r = t >> 3, cc = t & 7;
        size_t ga = (grow0 + (size_t)ch * 64 + r) * NTOT + h * HD + cc * 8;
        uint32_t off = ((uint32_t)buf * 4096 + r * 64 + ((cc ^ (r & 7)) * 8)) * 2;
        asm volatile("cp.async.cg.shared.global [%0], [%1], 16;"
                     :: "r"(wbase + off), "l"(d_LVh + ga));
        asm volatile("cp.async.cg.shared.global [%0], [%1], 16;"
                     :: "r"(vbase + off), "l"(d_LVh + ga + 512));
    }
    asm volatile("cp.async.commit_group;" ::: "memory");
}

__global__ __launch_bounds__(128) void accum_mma() {
    __shared__ __half Wst[2][64 * 64];
    __shared__ __half Vst[2][64 * 64];
    int sc = blockIdx.x, h = blockIdx.y, b = blockIdx.z;
    int tid = threadIdx.x, warp = tid >> 5, lane = tid & 31;
    int q1 = (lane >> 3) & 1, q2 = lane >> 4;
    uint32_t wbase = s2u(Wst), vbase = s2u(Vst);
    size_t grow0 = (size_t)b * SEQ + sc * 1024;

    float acc[8][4];
    #pragma unroll
    for (int nt = 0; nt < 8; nt++)
        #pragma unroll
        for (int i = 0; i < 4; i++) acc[nt][i] = 0.f;
    float cacc0 = 0.f, cacc1 = 0.f;

    acc_load(wbase, vbase, grow0, h, 0, 0, tid);
    for (int ch = 0; ch < 16; ch++) {
        int buf = ch & 1;
        if (ch + 1 < 16) {
            acc_load(wbase, vbase, grow0, h, ch + 1, buf ^ 1, tid);
            asm volatile("cp.async.wait_group 1;" ::: "memory");
        } else {
            asm volatile("cp.async.wait_group 0;" ::: "memory");
        }
        __syncthreads();
        #pragma unroll
        for (int ks = 0; ks < 4; ks++) {
            int s_loc = ks * 16 + q2 * 8 + (lane & 7);
            uint32_t a[4];
            {
                int cc = warp * 2 + q1;
                uint32_t ad = wbase + ((uint32_t)buf * 4096 + s_loc * 64 + ((cc ^ (s_loc & 7)) * 8)) * 2;
                LDSM4T(a[0], a[1], a[2], a[3], ad);
            }
            {   // slot-sum of W from A fragments
                float2 f;
                f = __half22float2(*(__half2*)&a[0]); cacc0 += f.x + f.y;
                f = __half22float2(*(__half2*)&a[2]); cacc0 += f.x + f.y;
                f = __half22float2(*(__half2*)&a[1]); cacc1 += f.x + f.y;
                f = __half22float2(*(__half2*)&a[3]); cacc1 += f.x + f.y;
            }
            #pragma unroll
            for (int p = 0; p < 4; p++) {
                uint32_t r0, r1, r2, r3;
                int cc = p * 2 + q1;
                uint32_t vd = vbase + ((uint32_t)buf * 4096 + s_loc * 64 + ((cc ^ (s_loc & 7)) * 8)) * 2;
                LDSM4T(r0, r1, r2, r3, vd);
                MMA16816(acc[2*p],     a, r0, r2);
                MMA16816(acc[2*p + 1], a, r1, r3);
            }
        }
        __syncthreads();
    }

    cacc0 += __shfl_xor_sync(0xffffffffu, cacc0, 1);
    cacc0 += __shfl_xor_sync(0xffffffffu, cacc0, 2);
    cacc1 += __shfl_xor_sync(0xffffffffu, cacc1, 1);
    cacc1 += __shfl_xor_sync(0xffffffffu, cacc1, 2);
    int slot0 = warp * 16 + (lane >> 2);
    if ((lane & 3) == 0) {
        atomicAdd(&d_C[b * DIM + h * HD + slot0],     cacc0);
        atomicAdd(&d_C[b * DIM + h * HD + slot0 + 8], cacc1);
    }
    #pragma unroll
    for (int nt = 0; nt < 8; nt++) {
        int dc = nt * 8 + (lane & 3) * 2;
        float* p0 = &d_Num[((size_t)b * DIM + h * HD + slot0) * HD + dc];
        float* p1 = &d_Num[((size_t)b * DIM + h * HD + slot0 + 8) * HD + dc];
        atomicAdd(p0,     acc[nt][0]);
        atomicAdd(p0 + 1, acc[nt][1]);
        atomicAdd(p1,     acc[nt][2]);
        atomicAdd(p1 + 1, acc[nt][3]);
    }
}

// ---------------- 7. divide, transpose, final LN ----------------
__global__ void final_kernel(const float* __restrict__ g,
                             const float* __restrict__ bb,
                             float* __restrict__ out) {
    __shared__ float sbuf[32];
    int blk = blockIdx.x;
    int b = blk >> 6, k = blk & 63;
    int tid = threadIdx.x;
    int h = tid >> 6, d = tid & 63;
    float c = d_C[b * DIM + h * HD + k];
    float v = d_Num[((size_t)b * DIM + h * HD + k) * HD + d] / (c + EPS_C);
    float mu = blockReduceSum(v, sbuf) * (1.f / DIM);
    float dv = v - mu;
    float var = blockReduceSum(dv * dv, sbuf) * (1.f / DIM);
    out[(size_t)blk * DIM + tid] = dv * rsqrtf(var + LN_EPS) * g[tid] + bb[tid];
}

// ---------------- launch ----------------
extern "C" void kernel_launch(void* const* d_in, const int* in_sizes, int n_in,
                              void* d_out, int out_size) {
    const float* X       = (const float*)d_in[0];
    const float* slots_w = (const float*)d_in[1];
    const float* g_slots = (const float*)d_in[2];
    const float* b_slots = (const float*)d_in[3];
    const float* Wk      = (const float*)d_in[4];
    const float* bk      = (const float*)d_in[5];
    const float* Wv      = (const float*)d_in[6];
    const float* bv      = (const float*)d_in[7];
    const float* g_after = (const float*)d_in[8];
    const float* b_after = (const float*)d_in[9];
    float* out = (float*)d_out;

    __half *pXh, *pWh, *pLVh;
    float *pbcat;
    cudaGetSymbolAddress((void**)&pXh, d_Xh);
    cudaGetSymbolAddress((void**)&pWh, d_Wh);
    cudaGetSymbolAddress((void**)&pbcat, d_bcat);
    cudaGetSymbolAddress((void**)&pLVh, d_LVh);

    static bool attr_set = false;
    if (!attr_set) {
        cudaFuncSetAttribute(gemm_fp16, cudaFuncAttributeMaxDynamicSharedMemorySize, SMEM_BYTES);
        attr_set = true;
    }

    ln_slots_kernel<<<KSLOTS, DIM>>>(slots_w, g_slots, b_slots);
    fold_kernel<<<DIM, 256>>>(Wk, bk);
    conv_all<<<CONVX_BLKS + CONVW_BLKS + ZERO_BLKS, 256>>>(X, Wv, bv);

    dim3 ggrid(NTOT / NT, BT / MT);   // (8, 512)
    gemm_fp16<<<ggrid, 256, SMEM_BYTES>>>(pXh, pWh, pbcat, pLVh);

    accum_mma<<<dim3(8, HEADS, BATCH), 128>>>();
    final_kernel<<<BATCH * KSLOTS, DIM>>>(g_after, b_after, out);
}